// round 3
// baseline (speedup 1.0000x reference)
#include <cuda_runtime.h>
#include <cuda_bf16.h>
#include <cfloat>

// ---------------------------------------------------------------------------
// Problem constants (fixed by the dataset):
//   N = 500000 rows, D = 64, G = 50000 groups, w1: [192,64], w2: [64,64]
// Algebra: h@w1 = x@(w1a+w1b+w1c) - min_g@w1b - max_g@w1c
//   => y1 = leaky(x@Wsum + bias[seg]),  out = leaky(y1@w2)
// ---------------------------------------------------------------------------

#define MAX_G 50000
#define MAX_N 500000

__device__ float g_bias[MAX_G * 64];   // per-group folded bias
__device__ int   g_seg[MAX_N];         // row -> group id
__device__ float g_Wsum[64 * 64];      // w1a + w1b + w1c

__device__ __forceinline__ float lrelu(float v) { return v > 0.0f ? v : 0.2f * v; }

// ---------------------------------------------------------------------------
// Kernel A: Wsum = w1[0:64] + w1[64:128] + w1[128:192]
// ---------------------------------------------------------------------------
__global__ void wsum_kernel(const float* __restrict__ w1) {
    int i = blockIdx.x * 256 + threadIdx.x;
    if (i < 4096) g_Wsum[i] = w1[i] + w1[4096 + i] + w1[8192 + i];
}

// ---------------------------------------------------------------------------
// Kernel B: per-group min/max + seg map + bias = -(min@w1b + max@w1c)
// One warp per group (strided). Lane l owns cols 2l, 2l+1.
// ---------------------------------------------------------------------------
__global__ __launch_bounds__(256) void minmax_bias_kernel(
    const float* __restrict__ x, const int* __restrict__ csr,
    const float* __restrict__ w1, int G)
{
    __shared__ float w1s[8192];      // rows 64..191 of w1 (w1b then w1c)
    __shared__ float mns[8][64];
    __shared__ float mxs[8][64];

    int tid = threadIdx.x;
    for (int i = tid; i < 8192; i += 256) w1s[i] = w1[4096 + i];
    __syncthreads();

    int w    = tid >> 5;
    int lane = tid & 31;
    int c    = lane * 2;
    int totalWarps = gridDim.x * 8;

    for (int g = blockIdx.x * 8 + w; g < G; g += totalWarps) {
        int s = csr[g];
        int e = csr[g + 1];

        float2 mn = make_float2( FLT_MAX,  FLT_MAX);
        float2 mx = make_float2(-FLT_MAX, -FLT_MAX);

        int r = s;
        for (; r + 1 < e; r += 2) {                     // 2-way unroll for MLP
            float2 v0 = *(const float2*)(x + r * 64 + c);
            float2 v1 = *(const float2*)(x + (r + 1) * 64 + c);
            mn.x = fminf(mn.x, fminf(v0.x, v1.x));
            mn.y = fminf(mn.y, fminf(v0.y, v1.y));
            mx.x = fmaxf(mx.x, fmaxf(v0.x, v1.x));
            mx.y = fmaxf(mx.y, fmaxf(v0.y, v1.y));
        }
        if (r < e) {
            float2 v = *(const float2*)(x + r * 64 + c);
            mn.x = fminf(mn.x, v.x);  mn.y = fminf(mn.y, v.y);
            mx.x = fmaxf(mx.x, v.x);  mx.y = fmaxf(mx.y, v.y);
        }
        if (s == e) { mn = make_float2(0.f, 0.f); mx = make_float2(0.f, 0.f); }

        // row -> group map
        for (int rr = s + lane; rr < e; rr += 32) g_seg[rr] = g;

        mns[w][c] = mn.x;  mns[w][c + 1] = mn.y;
        mxs[w][c] = mx.x;  mxs[w][c + 1] = mx.y;
        __syncwarp();

        float2 acc = make_float2(0.f, 0.f);
        #pragma unroll 8
        for (int k = 0; k < 64; ++k) {
            float  m  = mns[w][k];
            float  M  = mxs[w][k];
            float2 wb = *(const float2*)(w1s + (k << 6) + c);          // w1b row k
            float2 wc = *(const float2*)(w1s + 4096 + (k << 6) + c);   // w1c row k
            acc.x = fmaf(-m, wb.x, fmaf(-M, wc.x, acc.x));
            acc.y = fmaf(-m, wb.y, fmaf(-M, wc.y, acc.y));
        }
        *(float2*)(g_bias + (long long)g * 64 + c) = acc;
        __syncwarp();   // protect mns/mxs before next group iteration overwrites
    }
}

// ---------------------------------------------------------------------------
// Kernel C: fused y1 = leaky(x@Wsum + bias[seg]); out = leaky(y1@w2)
// 128-row x 64-col tile per 256-thread block; 8 rows x 4 cols per thread.
// ---------------------------------------------------------------------------
#define XT_STRIDE 132                      // padded to kill transpose-store conflicts
#define SMEM_D_FLOATS (2 * 64 * XT_STRIDE + 2 * 64 * 64)
#define SMEM_D_BYTES  (SMEM_D_FLOATS * 4)  // 100352 bytes

#define FMA4(A, S, B) { (A).x += (S) * (B).x; (A).y += (S) * (B).y; \
                        (A).z += (S) * (B).z; (A).w += (S) * (B).w; }

__device__ __forceinline__ void tile_gemm(const float* __restrict__ At,   // [k][r], stride XT_STRIDE
                                          const float* __restrict__ Bm,   // [k][c], stride 64
                                          float4 acc[8], int r0, int c0)
{
    #pragma unroll 8
    for (int k = 0; k < 64; ++k) {
        float4 a0 = *(const float4*)(At + k * XT_STRIDE + r0);
        float4 a1 = *(const float4*)(At + k * XT_STRIDE + r0 + 4);
        float4 b  = *(const float4*)(Bm + (k << 6) + c0);
        FMA4(acc[0], a0.x, b);  FMA4(acc[1], a0.y, b);
        FMA4(acc[2], a0.z, b);  FMA4(acc[3], a0.w, b);
        FMA4(acc[4], a1.x, b);  FMA4(acc[5], a1.y, b);
        FMA4(acc[6], a1.z, b);  FMA4(acc[7], a1.w, b);
    }
}

__global__ __launch_bounds__(256) void fused_gemm_kernel(
    const float* __restrict__ x, const float* __restrict__ w2,
    float* __restrict__ out, int n)
{
    extern __shared__ float smem[];
    float* xT  = smem;                       // 64 x 132   (x transposed)
    float* y1T = smem + 64 * XT_STRIDE;      // 64 x 132   (y1 transposed)
    float* Ws  = smem + 2 * 64 * XT_STRIDE;  // 64 x 64
    float* w2s = Ws + 4096;                  // 64 x 64

    int tid = threadIdx.x;
    for (int i = tid; i < 4096; i += 256) { Ws[i] = g_Wsum[i]; w2s[i] = w2[i]; }

    int R0 = blockIdx.x * 128;

    // load x tile, transposed into SMEM (global reads fully coalesced)
    for (int i = tid; i < 2048; i += 256) {       // 2048 float4 slots = 128 rows x 16
        int r  = i >> 4;
        int c4 = i & 15;
        int gr = R0 + r;
        float4 v = make_float4(0.f, 0.f, 0.f, 0.f);
        if (gr < n) v = *(const float4*)(x + (long long)gr * 64 + c4 * 4);
        int c = c4 * 4;
        xT[(c + 0) * XT_STRIDE + r] = v.x;
        xT[(c + 1) * XT_STRIDE + r] = v.y;
        xT[(c + 2) * XT_STRIDE + r] = v.z;
        xT[(c + 3) * XT_STRIDE + r] = v.w;
    }
    __syncthreads();

    int tx = tid & 15, ty = tid >> 4;
    int c0 = tx * 4;
    int r0 = ty * 8;

    // GEMM 1: acc initialized from the folded per-group bias
    float4 acc[8];
    #pragma unroll
    for (int i = 0; i < 8; ++i) {
        int gr = R0 + r0 + i;
        float4 b = make_float4(0.f, 0.f, 0.f, 0.f);
        if (gr < n) {
            int g = g_seg[gr];
            b = *(const float4*)(g_bias + (long long)g * 64 + c0);
        }
        acc[i] = b;
    }

    tile_gemm(xT, Ws, acc, r0, c0);

    // leaky + stage y1 transposed (vectorize over the 8 contiguous rows)
    #pragma unroll
    for (int j = 0; j < 4; ++j) {
        float4 lo = make_float4(lrelu(acc[0].x), lrelu(acc[1].x), lrelu(acc[2].x), lrelu(acc[3].x));
        float4 hi = make_float4(lrelu(acc[4].x), lrelu(acc[5].x), lrelu(acc[6].x), lrelu(acc[7].x));
        // shift components: handle per-j manually below
        if (j == 1) { lo = make_float4(lrelu(acc[0].y), lrelu(acc[1].y), lrelu(acc[2].y), lrelu(acc[3].y));
                      hi = make_float4(lrelu(acc[4].y), lrelu(acc[5].y), lrelu(acc[6].y), lrelu(acc[7].y)); }
        if (j == 2) { lo = make_float4(lrelu(acc[0].z), lrelu(acc[1].z), lrelu(acc[2].z), lrelu(acc[3].z));
                      hi = make_float4(lrelu(acc[4].z), lrelu(acc[5].z), lrelu(acc[6].z), lrelu(acc[7].z)); }
        if (j == 3) { lo = make_float4(lrelu(acc[0].w), lrelu(acc[1].w), lrelu(acc[2].w), lrelu(acc[3].w));
                      hi = make_float4(lrelu(acc[4].w), lrelu(acc[5].w), lrelu(acc[6].w), lrelu(acc[7].w)); }
        *(float4*)(y1T + (c0 + j) * XT_STRIDE + r0)     = lo;
        *(float4*)(y1T + (c0 + j) * XT_STRIDE + r0 + 4) = hi;
    }
    __syncthreads();

    // GEMM 2
    float4 acc2[8];
    #pragma unroll
    for (int i = 0; i < 8; ++i) acc2[i] = make_float4(0.f, 0.f, 0.f, 0.f);

    tile_gemm(y1T, w2s, acc2, r0, c0);

    // leaky + coalesced float4 store
    #pragma unroll
    for (int i = 0; i < 8; ++i) {
        int gr = R0 + r0 + i;
        if (gr < n) {
            float4 o = make_float4(lrelu(acc2[i].x), lrelu(acc2[i].y),
                                   lrelu(acc2[i].z), lrelu(acc2[i].w));
            *(float4*)(out + (long long)gr * 64 + c0) = o;
        }
    }
}

// ---------------------------------------------------------------------------
// Launch
// ---------------------------------------------------------------------------
extern "C" void kernel_launch(void* const* d_in, const int* in_sizes, int n_in,
                              void* d_out, int out_size)
{
    const float* x   = (const float*)d_in[0];
    const int*   csr = (const int*)  d_in[1];
    const float* w1  = (const float*)d_in[2];
    const float* w2  = (const float*)d_in[3];
    float*       out = (float*)d_out;

    int n = in_sizes[0] / 64;      // 500000
    int G = in_sizes[1] - 1;       // 50000

    cudaFuncSetAttribute(fused_gemm_kernel,
                         cudaFuncAttributeMaxDynamicSharedMemorySize, SMEM_D_BYTES);

    wsum_kernel<<<16, 256>>>(w1);
    minmax_bias_kernel<<<1024, 256>>>(x, csr, w1, G);
    fused_gemm_kernel<<<(n + 127) / 128, 256, SMEM_D_BYTES>>>(x, w2, out, n);
}

// round 5
// speedup vs baseline: 1.2275x; 1.2275x over previous
#include <cuda_runtime.h>
#include <cuda_bf16.h>
#include <cfloat>

// ---------------------------------------------------------------------------
//   N = 500000 rows, D = 64, G = 50000 groups, w1: [192,64], w2: [64,64]
// Algebra: h@w1 = x@(w1a+w1b+w1c) - min_g@w1b - max_g@w1c
//   => y1 = leaky(x@Wsum + bias[seg]),  out = leaky(y1@w2)
// ---------------------------------------------------------------------------

#define MAX_G 50000
#define MAX_N 500000

__device__ float g_bias[MAX_G * 64];   // per-group folded bias
__device__ int   g_seg[MAX_N];         // row -> group id

__device__ __forceinline__ float lrelu(float v) { return v > 0.0f ? v : 0.2f * v; }

// ---- packed f32x2 helpers (sm_103a 2x FP32 path; PTX-only) ----------------
__device__ __forceinline__ unsigned long long pack2(float lo, float hi) {
    unsigned long long r;
    asm("mov.b64 %0, {%1, %2};" : "=l"(r) : "f"(lo), "f"(hi));
    return r;
}
__device__ __forceinline__ void ffma2(unsigned long long& acc,
                                      unsigned long long a, unsigned long long b) {
    asm("fma.rn.f32x2 %0, %1, %2, %0;" : "+l"(acc) : "l"(a), "l"(b));
}
__device__ __forceinline__ float2 unpack2(unsigned long long p) {
    float lo, hi;
    asm("mov.b64 {%0, %1}, %2;" : "=f"(lo), "=f"(hi) : "l"(p));
    return make_float2(lo, hi);
}

// ---------------------------------------------------------------------------
// Kernel B: per-group min/max + seg map + bias = -(min@w1b + max@w1c)
// One warp per group (strided). Lane l owns cols 2l, 2l+1.
// ---------------------------------------------------------------------------
__global__ __launch_bounds__(256) void minmax_bias_kernel(
    const float* __restrict__ x, const int* __restrict__ csr,
    const float* __restrict__ w1, int G)
{
    __shared__ float w1s[8192];      // rows 64..191 of w1 (w1b then w1c)
    __shared__ float mns[8][64];
    __shared__ float mxs[8][64];

    int tid = threadIdx.x;
    for (int i = tid; i < 8192; i += 256) w1s[i] = w1[4096 + i];
    __syncthreads();

    int w    = tid >> 5;
    int lane = tid & 31;
    int c    = lane * 2;
    int totalWarps = gridDim.x * 8;

    for (int g = blockIdx.x * 8 + w; g < G; g += totalWarps) {
        int s = csr[g];
        int e = csr[g + 1];

        float2 mn = make_float2( FLT_MAX,  FLT_MAX);
        float2 mx = make_float2(-FLT_MAX, -FLT_MAX);

        int r = s;
        for (; r + 1 < e; r += 2) {
            float2 v0 = *(const float2*)(x + r * 64 + c);
            float2 v1 = *(const float2*)(x + (r + 1) * 64 + c);
            mn.x = fminf(mn.x, fminf(v0.x, v1.x));
            mn.y = fminf(mn.y, fminf(v0.y, v1.y));
            mx.x = fmaxf(mx.x, fmaxf(v0.x, v1.x));
            mx.y = fmaxf(mx.y, fmaxf(v0.y, v1.y));
        }
        if (r < e) {
            float2 v = *(const float2*)(x + r * 64 + c);
            mn.x = fminf(mn.x, v.x);  mn.y = fminf(mn.y, v.y);
            mx.x = fmaxf(mx.x, v.x);  mx.y = fmaxf(mx.y, v.y);
        }
        if (s == e) { mn = make_float2(0.f, 0.f); mx = make_float2(0.f, 0.f); }

        for (int rr = s + lane; rr < e; rr += 32) g_seg[rr] = g;

        mns[w][c] = mn.x;  mns[w][c + 1] = mn.y;
        mxs[w][c] = mx.x;  mxs[w][c + 1] = mx.y;
        __syncwarp();

        float2 acc = make_float2(0.f, 0.f);
        #pragma unroll 8
        for (int k = 0; k < 64; ++k) {
            float  m  = mns[w][k];
            float  M  = mxs[w][k];
            float2 wb = *(const float2*)(w1s + (k << 6) + c);          // w1b row k
            float2 wc = *(const float2*)(w1s + 4096 + (k << 6) + c);   // w1c row k
            acc.x = fmaf(-m, wb.x, fmaf(-M, wc.x, acc.x));
            acc.y = fmaf(-m, wb.y, fmaf(-M, wc.y, acc.y));
        }
        *(float2*)(g_bias + (long long)g * 64 + c) = acc;
        __syncwarp();
    }
}

// ---------------------------------------------------------------------------
// Kernel C: fused y1 = leaky(x@Wsum + bias[seg]); out = leaky(y1@w2)
// 256-row x 64-col tile / 256 threads; 8 rows (stride 32) x 8 cols per thread.
// A read as row-major scalars (warp-broadcast across the 8 col-lanes -> free
// on the crossbar). Accumulators are packed f32x2 column pairs.
// ---------------------------------------------------------------------------
#define XS_STRIDE 68
#define SMEM_FLOATS (256 * XS_STRIDE + 2 * 4096)
#define SMEM_BYTES  (SMEM_FLOATS * 4)   // 102400

__device__ __forceinline__ void gemm_tile(const float* __restrict__ A,   // [256][XS_STRIDE]
                                          const float* __restrict__ B,   // [64][64]
                                          unsigned long long acc[8][4],
                                          int br, int c0)
{
    #pragma unroll 8
    for (int k = 0; k < 64; ++k) {
        ulonglong2 bA = *(const ulonglong2*)(B + (k << 6) + c0);       // cols c0..c0+3
        ulonglong2 bB = *(const ulonglong2*)(B + (k << 6) + c0 + 4);   // cols c0+4..c0+7
        #pragma unroll
        for (int i = 0; i < 8; ++i) {
            float a = A[(br + 32 * i) * XS_STRIDE + k];
            unsigned long long ad = pack2(a, a);
            ffma2(acc[i][0], ad, bA.x);
            ffma2(acc[i][1], ad, bA.y);
            ffma2(acc[i][2], ad, bB.x);
            ffma2(acc[i][3], ad, bB.y);
        }
    }
}

__global__ __launch_bounds__(256, 2) void fused_gemm_kernel(
    const float* __restrict__ x, const float* __restrict__ w1,
    const float* __restrict__ w2, float* __restrict__ out, int n)
{
    extern __shared__ float smem[];
    float* xs  = smem;                      // 256 x 68 (row-major x, then y1)
    float* Ws  = smem + 256 * XS_STRIDE;    // 64 x 64   Wsum
    float* w2s = Ws + 4096;                 // 64 x 64

    int tid = threadIdx.x;
    int R0  = blockIdx.x * 256;

    // weights: Wsum computed in-block (w1 is L2-resident), w2 copied
    for (int i = tid; i < 4096; i += 256) {
        Ws[i]  = w1[i] + w1[4096 + i] + w1[8192 + i];
        w2s[i] = w2[i];
    }

    // x tile, row-major, coalesced float4 loads
    #pragma unroll
    for (int j = 0; j < 16; ++j) {
        int i  = tid + j * 256;             // 4096 float4 slots
        int r  = i >> 4;
        int c4 = (i & 15) * 4;
        int gr = R0 + r;
        float4 v = make_float4(0.f, 0.f, 0.f, 0.f);
        if (gr < n) v = *(const float4*)(x + (long long)gr * 64 + c4);
        *(float4*)(xs + r * XS_STRIDE + c4) = v;
    }
    __syncthreads();

    int tx = tid & 7;                        // col group
    int br = tid >> 3;                       // base row 0..31 (rows br+32i)
    int c0 = tx * 8;

    // GEMM 1: init from folded per-group bias
    unsigned long long acc[8][4];
    #pragma unroll
    for (int i = 0; i < 8; ++i) {
        int gr = R0 + br + 32 * i;
        if (gr < n) {
            int g = g_seg[gr];
            ulonglong2 b0 = *(const ulonglong2*)(g_bias + (long long)g * 64 + c0);
            ulonglong2 b1 = *(const ulonglong2*)(g_bias + (long long)g * 64 + c0 + 4);
            acc[i][0] = b0.x; acc[i][1] = b0.y; acc[i][2] = b1.x; acc[i][3] = b1.y;
        } else {
            acc[i][0] = acc[i][1] = acc[i][2] = acc[i][3] = 0ull;
        }
    }

    gemm_tile(xs, Ws, acc, br, c0);

    __syncthreads();   // everyone done reading xs

    // leaky + stage y1 over xs
    #pragma unroll
    for (int i = 0; i < 8; ++i) {
        int row = br + 32 * i;
        float2 p0 = unpack2(acc[i][0]);
        float2 p1 = unpack2(acc[i][1]);
        float2 p2 = unpack2(acc[i][2]);
        float2 p3 = unpack2(acc[i][3]);
        float4 lo = make_float4(lrelu(p0.x), lrelu(p0.y), lrelu(p1.x), lrelu(p1.y));
        float4 hi = make_float4(lrelu(p2.x), lrelu(p2.y), lrelu(p3.x), lrelu(p3.y));
        *(float4*)(xs + row * XS_STRIDE + c0)     = lo;
        *(float4*)(xs + row * XS_STRIDE + c0 + 4) = hi;
    }
    __syncthreads();

    // GEMM 2
    #pragma unroll
    for (int i = 0; i < 8; ++i)
        acc[i][0] = acc[i][1] = acc[i][2] = acc[i][3] = 0ull;

    gemm_tile(xs, w2s, acc, br, c0);

    // leaky + coalesced store
    #pragma unroll
    for (int i = 0; i < 8; ++i) {
        int gr = R0 + br + 32 * i;
        if (gr < n) {
            float2 p0 = unpack2(acc[i][0]);
            float2 p1 = unpack2(acc[i][1]);
            float2 p2 = unpack2(acc[i][2]);
            float2 p3 = unpack2(acc[i][3]);
            float4 lo = make_float4(lrelu(p0.x), lrelu(p0.y), lrelu(p1.x), lrelu(p1.y));
            float4 hi = make_float4(lrelu(p2.x), lrelu(p2.y), lrelu(p3.x), lrelu(p3.y));
            *(float4*)(out + (long long)gr * 64 + c0)     = lo;
            *(float4*)(out + (long long)gr * 64 + c0 + 4) = hi;
        }
    }
}

// ---------------------------------------------------------------------------
// Launch
// ---------------------------------------------------------------------------
extern "C" void kernel_launch(void* const* d_in, const int* in_sizes, int n_in,
                              void* d_out, int out_size)
{
    const float* x   = (const float*)d_in[0];
    const int*   csr = (const int*)  d_in[1];
    const float* w1  = (const float*)d_in[2];
    const float* w2  = (const float*)d_in[3];
    float*       out = (float*)d_out;

    int n = in_sizes[0] / 64;      // 500000
    int G = in_sizes[1] - 1;       // 50000

    cudaFuncSetAttribute(fused_gemm_kernel,
                         cudaFuncAttributeMaxDynamicSharedMemorySize, SMEM_BYTES);

    minmax_bias_kernel<<<1024, 256>>>(x, csr, w1, G);
    fused_gemm_kernel<<<(n + 255) / 256, 256, SMEM_BYTES>>>(x, w1, w2, out, n);
}